// round 2
// baseline (speedup 1.0000x reference)
#include <cuda_runtime.h>

#define NC 4
#define CS 512
#define NS 256
#define HD 512
#define H  256
#define GAMMA_C 12.0f

// Tile config for score kernel
#define TI 32          // i-rows per CTA
#define TJ 32          // j-cols per CTA
#define TK 64          // k per stage
#define TKP 66         // padded row stride (floats): 2-bank shift per row -> conflict-free LDS64

// Scratch: rotated heads (allowed: __device__ globals, no allocation)
__device__ float g_real[NC * CS * H];
__device__ float g_imag[NC * CS * H];

// ---------------- Kernel A: rotate heads by relation phase ----------------
__global__ void rotate_kernel(const float* __restrict__ heads,
                              const float* __restrict__ rel) {
    int i = blockIdx.x;      // 0..2047
    int k = threadIdx.x;     // 0..255
    float re = heads[i * HD + k];
    float im = heads[i * HD + H + k];
    // phase = rel / (EMB_INIT/pi) = rel * (pi/0.05)
    float ph = rel[i * H + k] * 62.8318530717958648f;
    float s, c;
    sincosf(ph, &s, &c);
    g_real[i * H + k] = re * c - im * s;
    g_imag[i * H + k] = re * s + im * c;
}

// ---------------- f32x2 helpers (FFMA2 path, sm_100+) ----------------
__device__ __forceinline__ unsigned long long addx2(unsigned long long a, unsigned long long b) {
    unsigned long long d;
    asm("add.rn.f32x2 %0, %1, %2;" : "=l"(d) : "l"(a), "l"(b));
    return d;
}
__device__ __forceinline__ unsigned long long mulx2(unsigned long long a, unsigned long long b) {
    unsigned long long d;
    asm("mul.rn.f32x2 %0, %1, %2;" : "=l"(d) : "l"(a), "l"(b));
    return d;
}
__device__ __forceinline__ unsigned long long fmax2(unsigned long long a, unsigned long long b, unsigned long long c) {
    unsigned long long d;
    asm("fma.rn.f32x2 %0, %1, %2, %3;" : "=l"(d) : "l"(a), "l"(b), "l"(c));
    return d;
}
__device__ __forceinline__ float sqrt_fast(float x) {
    float y;
    asm("sqrt.approx.f32 %0, %1;" : "=f"(y) : "f"(x));
    return y;
}
__device__ __forceinline__ unsigned long long lds64(const float* p) {
    return *reinterpret_cast<const unsigned long long*>(p);
}

// ---------------- Kernel B: tiled score, 2i x 2j register blocking ----------------
__global__ __launch_bounds__(256, 4) void score_kernel(const float* __restrict__ tails,
                                                       float* __restrict__ out) {
    __shared__ float s_re[TI][TKP];
    __shared__ float s_im[TI][TKP];
    __shared__ float s_tr[TJ][TKP];   // negated tail real
    __shared__ float s_ti[TJ][TKP];   // negated tail imag

    const int tid = threadIdx.x;
    const int c   = blockIdx.z;           // chunk
    const int bi  = blockIdx.x;           // 0..15
    const int bj  = blockIdx.y;           // 0..7

    const int tjx = tid & 15;             // j in tile: tjx and tjx+16
    const int tix = tid >> 4;             // i in tile: tix and tix+16

    const int gi0 = c * CS + bi * TI;     // global head-row base
    const float* tbase = tails + (size_t)(c * NS + bj * TJ) * HD;

    float acc[2][2][2];
    #pragma unroll
    for (int i = 0; i < 2; i++)
        #pragma unroll
        for (int j = 0; j < 2; j++) { acc[i][j][0] = 0.f; acc[i][j][1] = 0.f; }

    for (int k0 = 0; k0 < H; k0 += TK) {
        __syncthreads();
        // stage: each of 4 arrays is 32 rows x 64 floats = 1024 float2; 4 per thread
        #pragma unroll
        for (int t = 0; t < 4; t++) {
            int idx = tid + t * 256;         // 0..1023
            int r   = idx >> 5;              // 0..31
            int c2  = (idx & 31) * 2;        // 0..62
            float2 v = *reinterpret_cast<const float2*>(&g_real[(size_t)(gi0 + r) * H + k0 + c2]);
            *reinterpret_cast<float2*>(&s_re[r][c2]) = v;
            float2 w = *reinterpret_cast<const float2*>(&g_imag[(size_t)(gi0 + r) * H + k0 + c2]);
            *reinterpret_cast<float2*>(&s_im[r][c2]) = w;
            float2 a = *reinterpret_cast<const float2*>(&tbase[(size_t)r * HD + k0 + c2]);
            *reinterpret_cast<float2*>(&s_tr[r][c2]) = make_float2(-a.x, -a.y);
            float2 b = *reinterpret_cast<const float2*>(&tbase[(size_t)r * HD + H + k0 + c2]);
            *reinterpret_cast<float2*>(&s_ti[r][c2]) = make_float2(-b.x, -b.y);
        }
        __syncthreads();

        #pragma unroll 8
        for (int kk = 0; kk < TK; kk += 2) {
            unsigned long long tr0 = lds64(&s_tr[tjx][kk]);
            unsigned long long ti0 = lds64(&s_ti[tjx][kk]);
            unsigned long long tr1 = lds64(&s_tr[tjx + 16][kk]);
            unsigned long long ti1 = lds64(&s_ti[tjx + 16][kk]);
            unsigned long long rr0 = lds64(&s_re[tix][kk]);
            unsigned long long rm0 = lds64(&s_im[tix][kk]);
            unsigned long long rr1 = lds64(&s_re[tix + 16][kk]);
            unsigned long long rm1 = lds64(&s_im[tix + 16][kk]);

            #pragma unroll
            for (int i = 0; i < 2; i++) {
                unsigned long long rr = i ? rr1 : rr0;
                unsigned long long rm = i ? rm1 : rm0;
                #pragma unroll
                for (int j = 0; j < 2; j++) {
                    unsigned long long dr = addx2(rr, j ? tr1 : tr0);
                    unsigned long long di = addx2(rm, j ? ti1 : ti0);
                    unsigned long long s2 = mulx2(dr, dr);
                    s2 = fmax2(di, di, s2);
                    float lo, hi;
                    asm("mov.b64 {%0, %1}, %2;" : "=f"(lo), "=f"(hi) : "l"(s2));
                    acc[i][j][0] += sqrt_fast(lo);
                    acc[i][j][1] += sqrt_fast(hi);
                }
            }
        }
    }

    const int gj = bj * TJ + tjx;
    const int gi = bi * TI + tix;
    #pragma unroll
    for (int i = 0; i < 2; i++)
        #pragma unroll
        for (int j = 0; j < 2; j++)
            out[((size_t)c * CS + gi + i * 16) * NS + gj + j * 16] =
                GAMMA_C - (acc[i][j][0] + acc[i][j][1]);
}

extern "C" void kernel_launch(void* const* d_in, const int* in_sizes, int n_in,
                              void* d_out, int out_size) {
    const float* heads = (const float*)d_in[0];
    const float* rel   = (const float*)d_in[1];
    const float* tails = (const float*)d_in[2];
    float* out = (float*)d_out;

    rotate_kernel<<<NC * CS, H>>>(heads, rel);
    dim3 grid(CS / TI, NS / TJ, NC);   // (16, 8, 4) = 512 CTAs, single wave at 4 CTAs/SM
    score_kernel<<<grid, 256>>>(tails, out);
}

// round 3
// speedup vs baseline: 1.0700x; 1.0700x over previous
#include <cuda_runtime.h>

#define NC 4
#define CS 512
#define NS 256
#define HD 512
#define H  256
#define GAMMA_C 12.0f

// Tile config for score kernel
#define TI 32          // i-rows per CTA tile
#define TJ 16          // j-cols per CTA tile
#define TK 64          // k per stage
#define TKP 68         // padded row stride (floats): 4-bank row shift -> conflict-free LDS.128
#define NTILES (NC * (CS / TI) * (NS / TJ))   // 4*16*16 = 1024
#define GRID_P 740                            // 148 SMs * 5 CTAs/SM, persistent

// Scratch: rotated heads (allowed: __device__ globals, no allocation)
__device__ float g_real[NC * CS * H];
__device__ float g_imag[NC * CS * H];

// ---------------- Kernel A: rotate heads by relation phase ----------------
__global__ void rotate_kernel(const float* __restrict__ heads,
                              const float* __restrict__ rel) {
    int i = blockIdx.x;      // 0..2047
    int k = threadIdx.x;     // 0..255
    float re = heads[i * HD + k];
    float im = heads[i * HD + H + k];
    // phase = rel / (EMB_INIT/pi) = rel * (pi/0.05)
    float ph = rel[i * H + k] * 62.8318530717958648f;
    float s, c;
    __sincosf(ph, &s, &c);
    g_real[i * H + k] = re * c - im * s;
    g_imag[i * H + k] = re * s + im * c;
}

// ---------------- f32x2 helpers (FFMA2 path, sm_100+) ----------------
__device__ __forceinline__ unsigned long long addx2(unsigned long long a, unsigned long long b) {
    unsigned long long d;
    asm("add.rn.f32x2 %0, %1, %2;" : "=l"(d) : "l"(a), "l"(b));
    return d;
}
__device__ __forceinline__ unsigned long long mulx2(unsigned long long a, unsigned long long b) {
    unsigned long long d;
    asm("mul.rn.f32x2 %0, %1, %2;" : "=l"(d) : "l"(a), "l"(b));
    return d;
}
__device__ __forceinline__ unsigned long long fmax2(unsigned long long a, unsigned long long b, unsigned long long c) {
    unsigned long long d;
    asm("fma.rn.f32x2 %0, %1, %2, %3;" : "=l"(d) : "l"(a), "l"(b), "l"(c));
    return d;
}
__device__ __forceinline__ float sqrt_fast(float x) {
    float y;
    asm("sqrt.approx.f32 %0, %1;" : "=f"(y) : "f"(x));
    return y;
}

// complex |h - t| for a packed pair of k; tails pre-negated so sub becomes add
__device__ __forceinline__ void accum_pair(unsigned long long rr, unsigned long long rm,
                                           unsigned long long tr, unsigned long long ti,
                                           float& a0, float& a1) {
    unsigned long long dr = addx2(rr, tr);
    unsigned long long di = addx2(rm, ti);
    unsigned long long s2 = mulx2(dr, dr);
    s2 = fmax2(di, di, s2);
    float lo, hi;
    asm("mov.b64 {%0, %1}, %2;" : "=f"(lo), "=f"(hi) : "l"(s2));
    a0 += sqrt_fast(lo);
    a1 += sqrt_fast(hi);
}

// ---------------- Kernel B: persistent tiled score ----------------
__global__ __launch_bounds__(256, 5) void score_kernel(const float* __restrict__ tails,
                                                       float* __restrict__ out) {
    __shared__ __align__(16) float s_re[TI][TKP];
    __shared__ __align__(16) float s_im[TI][TKP];
    __shared__ __align__(16) float s_tr[TJ][TKP];   // negated tail real
    __shared__ __align__(16) float s_ti[TJ][TKP];   // negated tail imag

    const int tid = threadIdx.x;
    const int tjx = tid & 15;             // j in tile
    const int tix = tid >> 4;             // i in tile (rows tix, tix+16)

    for (int t = blockIdx.x; t < NTILES; t += GRID_P) {
        const int c   = t >> 8;           // chunk
        const int rem = t & 255;
        const int bi  = rem & 15;         // 0..15
        const int bj  = rem >> 4;         // 0..15

        const int gi0 = c * CS + bi * TI;
        const float* tbase = tails + (size_t)(c * NS + bj * TJ) * HD;

        float accA0 = 0.f, accA1 = 0.f;
        float accB0 = 0.f, accB1 = 0.f;

        for (int k0 = 0; k0 < H; k0 += TK) {
            __syncthreads();
            // stage real/imag: 32 rows x 64 floats = 512 float4 each; 2 per thread
            #pragma unroll
            for (int s = 0; s < 2; s++) {
                int idx = tid + s * 256;
                int r   = idx >> 4;             // 0..31
                int c4  = (idx & 15) * 4;       // 0..60
                float4 v = *reinterpret_cast<const float4*>(&g_real[(size_t)(gi0 + r) * H + k0 + c4]);
                *reinterpret_cast<float4*>(&s_re[r][c4]) = v;
                float4 w = *reinterpret_cast<const float4*>(&g_imag[(size_t)(gi0 + r) * H + k0 + c4]);
                *reinterpret_cast<float4*>(&s_im[r][c4]) = w;
            }
            // stage tails (negated): 16 rows x 64 floats = 256 float4; 1 per thread per array
            {
                int r  = tid >> 4;              // 0..15
                int c4 = (tid & 15) * 4;        // 0..60
                float4 v = *reinterpret_cast<const float4*>(&tbase[(size_t)r * HD + k0 + c4]);
                *reinterpret_cast<float4*>(&s_tr[r][c4]) = make_float4(-v.x, -v.y, -v.z, -v.w);
                float4 w = *reinterpret_cast<const float4*>(&tbase[(size_t)r * HD + H + k0 + c4]);
                *reinterpret_cast<float4*>(&s_ti[r][c4]) = make_float4(-w.x, -w.y, -w.z, -w.w);
            }
            __syncthreads();

            const float* ptr_tr  = &s_tr[tjx][0];
            const float* ptr_ti  = &s_ti[tjx][0];
            const float* ptr_re0 = &s_re[tix][0];
            const float* ptr_im0 = &s_im[tix][0];
            const float* ptr_re1 = &s_re[tix + 16][0];
            const float* ptr_im1 = &s_im[tix + 16][0];

            #pragma unroll
            for (int kk = 0; kk < TK; kk += 4) {
                ulonglong2 tr = *reinterpret_cast<const ulonglong2*>(ptr_tr + kk);
                ulonglong2 ti = *reinterpret_cast<const ulonglong2*>(ptr_ti + kk);
                ulonglong2 r0 = *reinterpret_cast<const ulonglong2*>(ptr_re0 + kk);
                ulonglong2 m0 = *reinterpret_cast<const ulonglong2*>(ptr_im0 + kk);
                ulonglong2 r1 = *reinterpret_cast<const ulonglong2*>(ptr_re1 + kk);
                ulonglong2 m1 = *reinterpret_cast<const ulonglong2*>(ptr_im1 + kk);

                accum_pair(r0.x, m0.x, tr.x, ti.x, accA0, accA1);
                accum_pair(r0.y, m0.y, tr.y, ti.y, accA0, accA1);
                accum_pair(r1.x, m1.x, tr.x, ti.x, accB0, accB1);
                accum_pair(r1.y, m1.y, tr.y, ti.y, accB0, accB1);
            }
        }

        const int gj = bj * TJ + tjx;
        const int gi = bi * TI + tix;
        out[((size_t)c * CS + gi)      * NS + gj] = GAMMA_C - (accA0 + accA1);
        out[((size_t)c * CS + gi + 16) * NS + gj] = GAMMA_C - (accB0 + accB1);
        __syncthreads();   // protect smem before next tile's staging
    }
}

extern "C" void kernel_launch(void* const* d_in, const int* in_sizes, int n_in,
                              void* d_out, int out_size) {
    const float* heads = (const float*)d_in[0];
    const float* rel   = (const float*)d_in[1];
    const float* tails = (const float*)d_in[2];
    float* out = (float*)d_out;

    rotate_kernel<<<NC * CS, H>>>(heads, rel);
    score_kernel<<<GRID_P, 256>>>(tails, out);
}